// round 2
// baseline (speedup 1.0000x reference)
#include <cuda_runtime.h>
#include <cuda_bf16.h>
#include <math.h>
#include <stdint.h>

// Problem constants
#define B_ 64
#define S_ 2048
#define H_ 1024
#define K_ 1024
#define Q_ 1024
#define HT 8          // number of 128-wide h tiles (H_/128)

// GEMM tile config
#define BM 128
#define BN 128
#define BK 16

// ---------------- device scratch (no allocations allowed) ----------------
__device__ float g_qp[B_ * H_];          // query @ Wq.T       [B,H]
__device__ float g_WkT[K_ * H_];         // Wk transposed      [K,H]
__device__ float g_epart[B_ * HT * S_];  // energy partials    [B,HT,S]
__device__ int   g_mask_flag;            // 1 => mask stored as 1-byte elems

// ---------------- packed f32x2 helpers ----------------
__device__ __forceinline__ void ffma2(unsigned long long& d,
                                      unsigned long long a,
                                      unsigned long long b) {
    asm("fma.rn.f32x2 %0, %1, %2, %0;" : "+l"(d) : "l"(a), "l"(b));
}
__device__ __forceinline__ unsigned long long pack2(float x, float y) {
    unsigned long long r;
    asm("mov.b64 %0, {%1, %2};" : "=l"(r) : "f"(x), "f"(y));
    return r;
}
__device__ __forceinline__ void unpack2(unsigned long long p, float& x, float& y) {
    asm("mov.b64 {%0, %1}, %2;" : "=f"(x), "=f"(y) : "l"(p));
}

__device__ __forceinline__ float warpMax(float v) {
    #pragma unroll
    for (int o = 16; o; o >>= 1) v = fmaxf(v, __shfl_xor_sync(0xFFFFFFFFu, v, o));
    return v;
}
__device__ __forceinline__ float warpSum(float v) {
    #pragma unroll
    for (int o = 16; o; o >>= 1) v += __shfl_xor_sync(0xFFFFFFFFu, v, o);
    return v;
}

// ---------------- 0. mask dtype probe ----------------
// Count nonzero bytes in the first B_*S_ bytes of the mask buffer.
// bool/int8 storage (Bernoulli(0.5)) -> ~50% nonzero bytes.
// int32 storage -> first quarter of the ints, ~12.5% nonzero bytes.
// (float32 0.0/1.0 -> ~25%, also below threshold; int path handles it.)
__global__ void probe_mask_kernel(const unsigned char* __restrict__ mask_bytes) {
    __shared__ int red[32];
    int tid = threadIdx.x;
    int cnt = 0;
    for (int i = tid; i < B_ * S_; i += blockDim.x)
        cnt += (mask_bytes[i] != 0);
    #pragma unroll
    for (int o = 16; o; o >>= 1) cnt += __shfl_xor_sync(0xFFFFFFFFu, cnt, o);
    if ((tid & 31) == 0) red[tid >> 5] = cnt;
    __syncthreads();
    if (tid == 0) {
        int total = 0;
        for (int i = 0; i < (int)(blockDim.x >> 5); i++) total += red[i];
        g_mask_flag = (total * 10 > 3 * (B_ * S_)) ? 1 : 0;  // >30% => bytes
    }
}

// ---------------- 1. transpose Wk [H,K] -> g_WkT [K,H] ----------------
__global__ void transpose_wk_kernel(const float* __restrict__ Wk) {
    __shared__ float t[32][33];
    int k0 = blockIdx.x * 32, h0 = blockIdx.y * 32;
    t[threadIdx.y][threadIdx.x] = Wk[(size_t)(h0 + threadIdx.y) * K_ + k0 + threadIdx.x];
    __syncthreads();
    g_WkT[(size_t)(k0 + threadIdx.y) * H_ + h0 + threadIdx.x] = t[threadIdx.x][threadIdx.y];
}

// ---------------- 2. qp[b,h] = sum_q query[b,q] * Wq[h,q] ----------------
__global__ void qproj_kernel(const float* __restrict__ query,
                             const float* __restrict__ Wq) {
    __shared__ float qs[Q_];
    int b = blockIdx.y;
    int h = blockIdx.x * blockDim.x + threadIdx.x;
    for (int i = threadIdx.x; i < Q_; i += blockDim.x) qs[i] = query[(size_t)b * Q_ + i];
    __syncthreads();
    const float4* wrow = (const float4*)(Wq + (size_t)h * Q_);
    const float4* q4 = (const float4*)qs;
    float acc = 0.f;
    #pragma unroll 4
    for (int q = 0; q < Q_ / 4; q++) {
        float4 w = wrow[q];
        float4 x = q4[q];
        acc = fmaf(w.x, x.x, acc);
        acc = fmaf(w.y, x.y, acc);
        acc = fmaf(w.z, x.z, acc);
        acc = fmaf(w.w, x.w, acc);
    }
    g_qp[(size_t)b * H_ + h] = acc;
}

// ---------------- 3. energy partials (the workhorse) ----------------
// Block computes C[128s x 128h] = keys[b, s0:+128, :] @ WkT[:, h0:+128],
// then fuses e_part[m] = sum_n v[h0+n] * tanh(qp[b,h0+n] + C[m,n]).
__global__ __launch_bounds__(256, 2)
void energy_kernel(const float* __restrict__ keys, const float* __restrict__ v) {
    __shared__ float As[BK][BM];  // 8 KB, keys tile transposed (k-major)
    __shared__ float Bs[BK][BN];  // 8 KB

    const int b  = blockIdx.z;
    const int s0 = blockIdx.x * BM;
    const int h0 = blockIdx.y * BN;
    const int tid = threadIdx.x;       // 0..255
    const int tx = tid & 15;           // col group (8 cols)
    const int ty = tid >> 4;           // row group (8 rows)
    const float* keysb = keys + (size_t)b * S_ * K_;

    unsigned long long acc[8][4];
    #pragma unroll
    for (int i = 0; i < 8; i++)
        #pragma unroll
        for (int j = 0; j < 4; j++) acc[i][j] = 0ull;

    for (int kt = 0; kt < K_ / BK; kt++) {
        __syncthreads();  // previous iteration's compute done
        // ---- load A tile: 128 rows x 16 k (512 float4, 2 per thread) ----
        #pragma unroll
        for (int u = 0; u < 2; u++) {
            int fi = tid * 2 + u;
            int row = fi >> 2;
            int kc = fi & 3;
            float4 val = *(const float4*)&keysb[(size_t)(s0 + row) * K_ + kt * BK + kc * 4];
            As[kc * 4 + 0][row] = val.x;
            As[kc * 4 + 1][row] = val.y;
            As[kc * 4 + 2][row] = val.z;
            As[kc * 4 + 3][row] = val.w;
        }
        // ---- load B tile: 16 k x 128 h (coalesced from WkT) ----
        #pragma unroll
        for (int u = 0; u < 2; u++) {
            int fi = tid * 2 + u;
            int kk = fi >> 5;
            int n4 = fi & 31;
            *(float4*)&Bs[kk][n4 * 4] =
                *(const float4*)&g_WkT[(size_t)(kt * BK + kk) * H_ + h0 + n4 * 4];
        }
        __syncthreads();
        // ---- compute: 16 k-steps, 8x8 per thread via packed f32x2 ----
        #pragma unroll
        for (int kk = 0; kk < BK; kk++) {
            float a[8];
            float4 a0 = *(const float4*)&As[kk][ty * 8];
            float4 a1 = *(const float4*)&As[kk][ty * 8 + 4];
            a[0] = a0.x; a[1] = a0.y; a[2] = a0.z; a[3] = a0.w;
            a[4] = a1.x; a[5] = a1.y; a[6] = a1.z; a[7] = a1.w;
            unsigned long long bp[4];
            const unsigned long long* bq = (const unsigned long long*)&Bs[kk][tx * 8];
            bp[0] = bq[0]; bp[1] = bq[1]; bp[2] = bq[2]; bp[3] = bq[3];
            #pragma unroll
            for (int i = 0; i < 8; i++) {
                unsigned long long ap = pack2(a[i], a[i]);
                #pragma unroll
                for (int j = 0; j < 4; j++) ffma2(acc[i][j], ap, bp[j]);
            }
        }
    }
    __syncthreads();

    // ---- fused epilogue: e_part[m] = sum_n v[n] * tanh(qp[n] + C[m,n]) ----
    float vv[8], qq[8];
    #pragma unroll
    for (int j = 0; j < 8; j++) {
        int h = h0 + tx * 8 + j;
        vv[j] = v[h];
        qq[j] = g_qp[(size_t)b * H_ + h];
    }
    float* red = &As[0][0];  // reuse: need 128*16 = 2048 floats
    #pragma unroll
    for (int i = 0; i < 8; i++) {
        float e = 0.f;
        #pragma unroll
        for (int j = 0; j < 4; j++) {
            float c0, c1;
            unpack2(acc[i][j], c0, c1);
            e = fmaf(vv[2 * j], tanhf(qq[2 * j] + c0), e);
            e = fmaf(vv[2 * j + 1], tanhf(qq[2 * j + 1] + c1), e);
        }
        red[(ty * 8 + i) * 16 + tx] = e;
    }
    __syncthreads();
    if (tid < BM) {
        float sum = 0.f;
        #pragma unroll
        for (int t = 0; t < 16; t++) sum += red[tid * 16 + t];
        g_epart[((size_t)b * HT + blockIdx.y) * S_ + s0 + tid] = sum;
    }
}

// ---------------- 4. masked softmax over S ----------------
__global__ void softmax_kernel(const void* __restrict__ mask,
                               float* __restrict__ out_attn) {
    __shared__ float es[S_];
    __shared__ float warpred[8];
    __shared__ float s_max, s_sum;
    const int b = blockIdx.x, tid = threadIdx.x;
    const int isbyte = g_mask_flag;
    const unsigned char* mb = (const unsigned char*)mask + (size_t)b * S_;
    const int* mi = (const int*)mask + (size_t)b * S_;

    float lmax = -INFINITY;
    for (int s = tid; s < S_; s += blockDim.x) {
        float e = 0.f;
        #pragma unroll
        for (int t = 0; t < HT; t++) e += g_epart[((size_t)b * HT + t) * S_ + s];
        bool pad = isbyte ? (mb[s] != 0) : (mi[s] != 0);
        if (pad) e = -INFINITY;
        es[s] = e;
        lmax = fmaxf(lmax, e);
    }
    lmax = warpMax(lmax);
    if ((tid & 31) == 0) warpred[tid >> 5] = lmax;
    __syncthreads();
    if (tid == 0) {
        float m = warpred[0];
        for (int i = 1; i < 8; i++) m = fmaxf(m, warpred[i]);
        s_max = m;
    }
    __syncthreads();
    const float m = s_max;
    float lsum = 0.f;
    for (int s = tid; s < S_; s += blockDim.x) {
        float e = es[s];
        float p = (e > -INFINITY) ? expf(e - m) : 0.f;
        es[s] = p;
        lsum += p;
    }
    lsum = warpSum(lsum);
    if ((tid & 31) == 0) warpred[tid >> 5] = lsum;
    __syncthreads();
    if (tid == 0) {
        float t = 0.f;
        for (int i = 0; i < 8; i++) t += warpred[i];
        s_sum = t;
    }
    __syncthreads();
    const float inv = (s_sum > 0.f) ? 1.f / s_sum : 0.f;  // all-pad row -> zeros
    for (int s = tid; s < S_; s += blockDim.x)
        out_attn[(size_t)b * S_ + s] = es[s] * inv;
}

// ---------------- 5. context[b,k] = sum_s attn[b,s] * keys[b,s,k] ----------------
__global__ void context_kernel(const float* __restrict__ keys,
                               const float* __restrict__ attn,
                               float* __restrict__ out_ctx) {
    __shared__ float a_s[S_];
    const int b = blockIdx.y;
    const int k = blockIdx.x * blockDim.x + threadIdx.x;
    for (int s = threadIdx.x; s < S_; s += blockDim.x)
        a_s[s] = attn[(size_t)b * S_ + s];
    __syncthreads();
    const float* kb = keys + (size_t)b * S_ * K_ + k;
    float acc = 0.f;
    #pragma unroll 8
    for (int s = 0; s < S_; s++) acc = fmaf(a_s[s], kb[(size_t)s * K_], acc);
    out_ctx[(size_t)b * K_ + k] = acc;
}

// ---------------- launcher ----------------
extern "C" void kernel_launch(void* const* d_in, const int* in_sizes, int n_in,
                              void* d_out, int out_size) {
    const float* query = (const float*)d_in[0];  // [B,Q]
    const float* keys  = (const float*)d_in[1];  // [B,S,K]
    const void*  mask  = d_in[2];                // [B,S] bool (dtype probed)
    const float* Wq    = (const float*)d_in[3];  // [H,Q]
    const float* Wk    = (const float*)d_in[4];  // [H,K]
    const float* v     = (const float*)d_in[5];  // [1,H]

    float* out      = (float*)d_out;
    float* out_ctx  = out;              // [B,K]
    float* out_attn = out + B_ * K_;    // [B,S]

    probe_mask_kernel<<<1, 1024>>>((const unsigned char*)mask);
    transpose_wk_kernel<<<dim3(K_ / 32, H_ / 32), dim3(32, 32)>>>(Wk);
    qproj_kernel<<<dim3(H_ / 256, B_), 256>>>(query, Wq);
    energy_kernel<<<dim3(S_ / BM, H_ / BN, B_), 256>>>(keys, v);
    softmax_kernel<<<B_, 256>>>(mask, out_attn);
    context_kernel<<<dim3(K_ / 256, B_), 256>>>(keys, out_attn, out_ctx);
}

// round 4
// speedup vs baseline: 2.1630x; 2.1630x over previous
#include <cuda_runtime.h>
#include <cuda_bf16.h>
#include <math.h>
#include <stdint.h>

// Problem constants
#define B_ 64
#define S_ 2048
#define H_ 1024
#define K_ 1024
#define Q_ 1024
#define HT 4          // number of 256-wide h tiles (H_/256)

// GEMM tile config (mma.sync m16n8k16 bf16)
#define BM 128
#define BN 256
#define BK 32
#define A_STR 40      // padded smem row stride (bf16 elems) -> conflict-free
#define B_STR 40

// smem byte offsets
#define oAHI 0
#define oALO (128 * A_STR * 2)              // 10240
#define oBHI (2 * 128 * A_STR * 2)          // 20480
#define oBLO (oBHI + 256 * B_STR * 2)       // 40960
#define oVS  (oBLO + 256 * B_STR * 2)       // 61440
#define oQS  (oVS + 1024)                   // 62464
#define oEP  (oQS + 1024)                   // 63488
#define SMEM_E (oEP + 128 * 4 * 4)          // 65536

// ---------------- device scratch ----------------
__device__ float g_qp[B_ * H_];
__device__ __nv_bfloat16 g_WkHi[H_ * K_];
__device__ __nv_bfloat16 g_WkLo[H_ * K_];
__device__ float g_epart[B_ * HT * S_];
__device__ int   g_mask_flag;

__device__ __forceinline__ void mma_bf16(float* c, const uint32_t* a,
                                         uint32_t b0, uint32_t b1) {
    asm volatile(
        "mma.sync.aligned.m16n8k16.row.col.f32.bf16.bf16.f32 "
        "{%0,%1,%2,%3}, {%4,%5,%6,%7}, {%8,%9}, {%0,%1,%2,%3};"
        : "+f"(c[0]), "+f"(c[1]), "+f"(c[2]), "+f"(c[3])
        : "r"(a[0]), "r"(a[1]), "r"(a[2]), "r"(a[3]), "r"(b0), "r"(b1));
}

__device__ __forceinline__ float warpMax(float v) {
    #pragma unroll
    for (int o = 16; o; o >>= 1) v = fmaxf(v, __shfl_xor_sync(0xFFFFFFFFu, v, o));
    return v;
}
__device__ __forceinline__ float warpSum(float v) {
    #pragma unroll
    for (int o = 16; o; o >>= 1) v += __shfl_xor_sync(0xFFFFFFFFu, v, o);
    return v;
}

// ---------------- 0. mask dtype probe ----------------
__global__ void probe_mask_kernel(const unsigned char* __restrict__ mask_bytes) {
    __shared__ int red[32];
    int tid = threadIdx.x;
    int cnt = 0;
    for (int i = tid; i < B_ * S_; i += blockDim.x)
        cnt += (mask_bytes[i] != 0);
    #pragma unroll
    for (int o = 16; o; o >>= 1) cnt += __shfl_xor_sync(0xFFFFFFFFu, cnt, o);
    if ((tid & 31) == 0) red[tid >> 5] = cnt;
    __syncthreads();
    if (tid == 0) {
        int total = 0;
        for (int i = 0; i < (int)(blockDim.x >> 5); i++) total += red[i];
        g_mask_flag = (total * 10 > 3 * (B_ * S_)) ? 1 : 0;
    }
}

// ---------------- 1. split Wk into bf16 hi/lo ----------------
__global__ void wk_split_kernel(const float* __restrict__ Wk) {
    int i = blockIdx.x * blockDim.x + threadIdx.x;
    float w = Wk[i];
    __nv_bfloat16 hi = __float2bfloat16(w);
    __nv_bfloat16 lo = __float2bfloat16(w - __bfloat162float(hi));
    g_WkHi[i] = hi;
    g_WkLo[i] = lo;
}

// ---------------- 2. qp[b,h] = sum_q query[b,q] * Wq[h,q] ----------------
__global__ void qproj_kernel(const float* __restrict__ query,
                             const float* __restrict__ Wq) {
    __shared__ float qs[Q_];
    int b = blockIdx.y;
    int h = blockIdx.x * blockDim.x + threadIdx.x;
    for (int i = threadIdx.x; i < Q_; i += blockDim.x) qs[i] = query[(size_t)b * Q_ + i];
    __syncthreads();
    const float4* wrow = (const float4*)(Wq + (size_t)h * Q_);
    const float4* q4 = (const float4*)qs;
    float acc = 0.f;
    #pragma unroll 4
    for (int q = 0; q < Q_ / 4; q++) {
        float4 w = wrow[q];
        float4 x = q4[q];
        acc = fmaf(w.x, x.x, acc);
        acc = fmaf(w.y, x.y, acc);
        acc = fmaf(w.z, x.z, acc);
        acc = fmaf(w.w, x.w, acc);
    }
    g_qp[(size_t)b * H_ + h] = acc;
}

// ---------------- 3. energy via mma.sync bf16 3-split GEMM ----------------
__global__ __launch_bounds__(512, 1)
void energy_mma_kernel(const float* __restrict__ keys, const float* __restrict__ v) {
    extern __shared__ char sm[];
    __nv_bfloat16* AHI = (__nv_bfloat16*)(sm + oAHI);
    __nv_bfloat16* ALO = (__nv_bfloat16*)(sm + oALO);
    __nv_bfloat16* BHI = (__nv_bfloat16*)(sm + oBHI);
    __nv_bfloat16* BLO = (__nv_bfloat16*)(sm + oBLO);
    float* vs = (float*)(sm + oVS);
    float* qs = (float*)(sm + oQS);
    float* ep = (float*)(sm + oEP);

    const int tid = threadIdx.x;
    const int wid = tid >> 5;
    const int lane = tid & 31;
    const int b = blockIdx.z;
    const int s0 = blockIdx.x * BM;
    const int h0 = blockIdx.y * BN;
    const float* keysb = keys + (size_t)b * S_ * K_;

    if (tid < 256) {
        vs[tid] = v[h0 + tid];
        qs[tid] = g_qp[(size_t)b * H_ + h0 + tid];
    }

    const int wm = wid & 3, wn = wid >> 2;
    const int mbase = wm * 32, nbase = wn * 64;
    const int gid = lane >> 2, qid = lane & 3;

    float acc[2][8][4];
    #pragma unroll
    for (int mf = 0; mf < 2; mf++)
        #pragma unroll
        for (int nf = 0; nf < 8; nf++)
            #pragma unroll
            for (int r = 0; r < 4; r++) acc[mf][nf][r] = 0.f;

    for (int kt = 0; kt < K_ / BK; kt++) {
        const int k0 = kt * BK;
        __syncthreads();
        // ---- A tile: 128 x 32 fp32 -> hi/lo bf16 ----
        #pragma unroll
        for (int i = 0; i < 2; i++) {
            int fi = i * 512 + tid;
            int row = fi >> 3;
            int c4 = fi & 7;
            float4 f = *(const float4*)(keysb + (size_t)(s0 + row) * K_ + k0 + c4 * 4);
            __nv_bfloat162 h01, h23, l01, l23;
            h01.x = __float2bfloat16(f.x); h01.y = __float2bfloat16(f.y);
            h23.x = __float2bfloat16(f.z); h23.y = __float2bfloat16(f.w);
            l01.x = __float2bfloat16(f.x - __bfloat162float(h01.x));
            l01.y = __float2bfloat16(f.y - __bfloat162float(h01.y));
            l23.x = __float2bfloat16(f.z - __bfloat162float(h23.x));
            l23.y = __float2bfloat16(f.w - __bfloat162float(h23.y));
            int off = row * A_STR + c4 * 4;
            *(uint2*)(AHI + off) = make_uint2(*(uint32_t*)&h01, *(uint32_t*)&h23);
            *(uint2*)(ALO + off) = make_uint2(*(uint32_t*)&l01, *(uint32_t*)&l23);
        }
        // ---- B tile: 256 x 32 bf16 hi/lo ----
        #pragma unroll
        for (int i = 0; i < 2; i++) {
            int fi = i * 512 + tid;
            int r = fi >> 2;
            int c8 = fi & 3;
            size_t gsrc = (size_t)(h0 + r) * K_ + k0 + c8 * 8;
            int off = r * B_STR + c8 * 8;
            *(int4*)(BHI + off) = *(const int4*)(g_WkHi + gsrc);
            *(int4*)(BLO + off) = *(const int4*)(g_WkLo + gsrc);
        }
        __syncthreads();
        // ---- compute: 2 k16 steps x 3 passes ----
        #pragma unroll
        for (int ks = 0; ks < 2; ks++) {
            const int kk = ks * 16 + 2 * qid;
            uint32_t aH[2][4], aL[2][4];
            #pragma unroll
            for (int mf = 0; mf < 2; mf++) {
                const __nv_bfloat16* pa = AHI + (mbase + mf * 16 + gid) * A_STR + kk;
                aH[mf][0] = *(const uint32_t*)pa;
                aH[mf][1] = *(const uint32_t*)(pa + 8 * A_STR);
                aH[mf][2] = *(const uint32_t*)(pa + 8);
                aH[mf][3] = *(const uint32_t*)(pa + 8 * A_STR + 8);
                const __nv_bfloat16* pl = ALO + (mbase + mf * 16 + gid) * A_STR + kk;
                aL[mf][0] = *(const uint32_t*)pl;
                aL[mf][1] = *(const uint32_t*)(pl + 8 * A_STR);
                aL[mf][2] = *(const uint32_t*)(pl + 8);
                aL[mf][3] = *(const uint32_t*)(pl + 8 * A_STR + 8);
            }
            #pragma unroll
            for (int nf = 0; nf < 8; nf++) {
                const __nv_bfloat16* pb = BHI + (nbase + nf * 8 + gid) * B_STR + kk;
                uint32_t bh0 = *(const uint32_t*)pb;
                uint32_t bh1 = *(const uint32_t*)(pb + 8);
                const __nv_bfloat16* pbl = BLO + (nbase + nf * 8 + gid) * B_STR + kk;
                uint32_t bl0 = *(const uint32_t*)pbl;
                uint32_t bl1 = *(const uint32_t*)(pbl + 8);
                #pragma unroll
                for (int mf = 0; mf < 2; mf++) {
                    mma_bf16(acc[mf][nf], aH[mf], bh0, bh1);
                    mma_bf16(acc[mf][nf], aH[mf], bl0, bl1);
                    mma_bf16(acc[mf][nf], aL[mf], bh0, bh1);
                }
            }
        }
    }

    // ---- fused epilogue: e[s] = sum_h v[h] * tanh(qp[h] + D[s,h]) ----
    float epr[2][2] = {{0.f, 0.f}, {0.f, 0.f}};
    #pragma unroll
    for (int mf = 0; mf < 2; mf++) {
        #pragma unroll
        for (int nf = 0; nf < 8; nf++) {
            int hh = nbase + nf * 8 + 2 * qid;
            float v0 = vs[hh], v1 = vs[hh + 1];
            float q0 = qs[hh], q1 = qs[hh + 1];
            epr[mf][0] = fmaf(v0, tanhf(q0 + acc[mf][nf][0]), epr[mf][0]);
            epr[mf][0] = fmaf(v1, tanhf(q1 + acc[mf][nf][1]), epr[mf][0]);
            epr[mf][1] = fmaf(v0, tanhf(q0 + acc[mf][nf][2]), epr[mf][1]);
            epr[mf][1] = fmaf(v1, tanhf(q1 + acc[mf][nf][3]), epr[mf][1]);
        }
    }
    #pragma unroll
    for (int mf = 0; mf < 2; mf++) {
        #pragma unroll
        for (int sbr = 0; sbr < 2; sbr++) {
            float val = epr[mf][sbr];
            val += __shfl_xor_sync(0xFFFFFFFFu, val, 1);
            val += __shfl_xor_sync(0xFFFFFFFFu, val, 2);
            if (qid == 0)
                ep[(mbase + mf * 16 + gid + sbr * 8) * 4 + wn] = val;
        }
    }
    __syncthreads();
    if (tid < BM) {
        float s = ep[tid * 4] + ep[tid * 4 + 1] + ep[tid * 4 + 2] + ep[tid * 4 + 3];
        g_epart[((size_t)b * HT + blockIdx.y) * S_ + s0 + tid] = s;
    }
}

// ---------------- 4. masked softmax over S ----------------
__global__ void softmax_kernel(const void* __restrict__ mask,
                               float* __restrict__ out_attn) {
    __shared__ float es[S_];
    __shared__ float warpred[8];
    __shared__ float s_max, s_sum;
    const int b = blockIdx.x, tid = threadIdx.x;
    const int isbyte = g_mask_flag;
    const unsigned char* mb = (const unsigned char*)mask + (size_t)b * S_;
    const int* mi = (const int*)mask + (size_t)b * S_;

    float lmax = -INFINITY;
    for (int s = tid; s < S_; s += blockDim.x) {
        float e = 0.f;
        #pragma unroll
        for (int t = 0; t < HT; t++) e += g_epart[((size_t)b * HT + t) * S_ + s];
        bool pad = isbyte ? (mb[s] != 0) : (mi[s] != 0);
        if (pad) e = -INFINITY;
        es[s] = e;
        lmax = fmaxf(lmax, e);
    }
    lmax = warpMax(lmax);
    if ((tid & 31) == 0) warpred[tid >> 5] = lmax;
    __syncthreads();
    if (tid == 0) {
        float m = warpred[0];
        for (int i = 1; i < 8; i++) m = fmaxf(m, warpred[i]);
        s_max = m;
    }
    __syncthreads();
    const float m = s_max;
    float lsum = 0.f;
    for (int s = tid; s < S_; s += blockDim.x) {
        float e = es[s];
        float p = (e > -INFINITY) ? expf(e - m) : 0.f;
        es[s] = p;
        lsum += p;
    }
    lsum = warpSum(lsum);
    if ((tid & 31) == 0) warpred[tid >> 5] = lsum;
    __syncthreads();
    if (tid == 0) {
        float t = 0.f;
        for (int i = 0; i < 8; i++) t += warpred[i];
        s_sum = t;
    }
    __syncthreads();
    const float inv = (s_sum > 0.f) ? 1.f / s_sum : 0.f;
    for (int s = tid; s < S_; s += blockDim.x)
        out_attn[(size_t)b * S_ + s] = es[s] * inv;
}

// ---------------- 5. context[b,k] = sum_s attn[b,s] * keys[b,s,k] ----------------
__global__ void context_kernel(const float* __restrict__ keys,
                               const float* __restrict__ attn,
                               float* __restrict__ out_ctx) {
    __shared__ float a_s[S_];
    const int b = blockIdx.y;
    const int k = blockIdx.x * blockDim.x + threadIdx.x;
    for (int s = threadIdx.x; s < S_; s += blockDim.x)
        a_s[s] = attn[(size_t)b * S_ + s];
    __syncthreads();
    const float* kb = keys + (size_t)b * S_ * K_ + k;
    float acc = 0.f;
    #pragma unroll 8
    for (int s = 0; s < S_; s++) acc = fmaf(a_s[s], kb[(size_t)s * K_], acc);
    out_ctx[(size_t)b * K_ + k] = acc;
}

// ---------------- launcher ----------------
extern "C" void kernel_launch(void* const* d_in, const int* in_sizes, int n_in,
                              void* d_out, int out_size) {
    const float* query = (const float*)d_in[0];  // [B,Q]
    const float* keys  = (const float*)d_in[1];  // [B,S,K]
    const void*  mask  = d_in[2];                // [B,S]
    const float* Wq    = (const float*)d_in[3];  // [H,Q]
    const float* Wk    = (const float*)d_in[4];  // [H,K]
    const float* v     = (const float*)d_in[5];  // [1,H]

    float* out      = (float*)d_out;
    float* out_ctx  = out;              // [B,K]
    float* out_attn = out + B_ * K_;    // [B,S]

    cudaFuncSetAttribute(energy_mma_kernel,
                         cudaFuncAttributeMaxDynamicSharedMemorySize, SMEM_E);

    probe_mask_kernel<<<1, 1024>>>((const unsigned char*)mask);
    wk_split_kernel<<<(H_ * K_) / 256, 256>>>(Wk);
    qproj_kernel<<<dim3(H_ / 256, B_), 256>>>(query, Wq);
    energy_mma_kernel<<<dim3(S_ / BM, H_ / BN, B_), 512, SMEM_E>>>(keys, v);
    softmax_kernel<<<B_, 256>>>(mask, out_attn);
    context_kernel<<<dim3(K_ / 256, B_), 256>>>(keys, out_attn, out_ctx);
}

// round 5
// speedup vs baseline: 2.6342x; 1.2178x over previous
#include <cuda_runtime.h>
#include <cuda_bf16.h>
#include <math.h>
#include <stdint.h>

// Problem constants
#define B_ 64
#define S_ 2048
#define H_ 1024
#define K_ 1024
#define Q_ 1024
#define HT 4          // number of 256-wide h tiles (H_/256)

// GEMM tile config (mma.sync m16n8k16 bf16, double-buffered)
#define BM 128
#define BN 256
#define BK 32
#define A_STR 40      // padded smem row stride (bf16) -> conflict-free
#define B_STR 40
#define NCHUNK (K_ / BK)

// smem byte offsets (dynamic)
// A: AHI[s] @ s*10240, ALO[s] @ 20480 + s*10240        (0 .. 40960)
// B: BHI[s] @ 40960 + s*20480, BLO[s] @ 81920 + s*20480 (40960 .. 122880)
#define oA   0
#define oALO 20480
#define oB   40960
#define oBLO 40960      // relative to oB region: BLO = oB + 40960 + s*20480
#define oVS  122880
#define oQS  123904
#define oEP  124928
#define SMEM_E 126976

// ---------------- device scratch ----------------
__device__ float g_qp[B_ * H_];
__device__ __nv_bfloat16 g_WkHi[H_ * K_];
__device__ __nv_bfloat16 g_WkLo[H_ * K_];
__device__ float g_epart[B_ * HT * S_];
__device__ int   g_mask_flag;

// ---------------- PTX helpers ----------------
__device__ __forceinline__ uint32_t smem_u32(const void* p) {
    uint32_t a;
    asm("{ .reg .u64 t; cvta.to.shared.u64 t, %1; cvt.u32.u64 %0, t; }" : "=r"(a) : "l"(p));
    return a;
}
__device__ __forceinline__ void mma_bf16(float* c, const uint32_t* a,
                                         uint32_t b0, uint32_t b1) {
    asm volatile(
        "mma.sync.aligned.m16n8k16.row.col.f32.bf16.bf16.f32 "
        "{%0,%1,%2,%3}, {%4,%5,%6,%7}, {%8,%9}, {%0,%1,%2,%3};"
        : "+f"(c[0]), "+f"(c[1]), "+f"(c[2]), "+f"(c[3])
        : "r"(a[0]), "r"(a[1]), "r"(a[2]), "r"(a[3]), "r"(b0), "r"(b1));
}
__device__ __forceinline__ void ldsm_x4(uint32_t* r, uint32_t addr) {
    asm volatile("ldmatrix.sync.aligned.m8n8.x4.shared.b16 {%0,%1,%2,%3}, [%4];"
                 : "=r"(r[0]), "=r"(r[1]), "=r"(r[2]), "=r"(r[3]) : "r"(addr));
}
#define CP_ASYNC16(dst, src) \
    asm volatile("cp.async.cg.shared.global [%0], [%1], 16;" :: "r"(dst), "l"(src))
#define CP_COMMIT() asm volatile("cp.async.commit_group;" ::: "memory")
#define CP_WAIT0()  asm volatile("cp.async.wait_group 0;" ::: "memory")

__device__ __forceinline__ float warpMax(float v) {
    #pragma unroll
    for (int o = 16; o; o >>= 1) v = fmaxf(v, __shfl_xor_sync(0xFFFFFFFFu, v, o));
    return v;
}
__device__ __forceinline__ float warpSum(float v) {
    #pragma unroll
    for (int o = 16; o; o >>= 1) v += __shfl_xor_sync(0xFFFFFFFFu, v, o);
    return v;
}

// ---------------- 0. mask dtype probe ----------------
__global__ void probe_mask_kernel(const unsigned char* __restrict__ mask_bytes) {
    __shared__ int red[32];
    int tid = threadIdx.x;
    int cnt = 0;
    for (int i = tid; i < B_ * S_; i += blockDim.x)
        cnt += (mask_bytes[i] != 0);
    #pragma unroll
    for (int o = 16; o; o >>= 1) cnt += __shfl_xor_sync(0xFFFFFFFFu, cnt, o);
    if ((tid & 31) == 0) red[tid >> 5] = cnt;
    __syncthreads();
    if (tid == 0) {
        int total = 0;
        for (int i = 0; i < (int)(blockDim.x >> 5); i++) total += red[i];
        g_mask_flag = (total * 10 > 3 * (B_ * S_)) ? 1 : 0;
    }
}

// ---------------- 1. split Wk into bf16 hi/lo ----------------
__global__ void wk_split_kernel(const float* __restrict__ Wk) {
    int i = blockIdx.x * blockDim.x + threadIdx.x;
    float w = Wk[i];
    __nv_bfloat16 hi = __float2bfloat16(w);
    __nv_bfloat16 lo = __float2bfloat16(w - __bfloat162float(hi));
    g_WkHi[i] = hi;
    g_WkLo[i] = lo;
}

// ---------------- 2. qp[b,h] = sum_q query[b,q] * Wq[h,q] ----------------
__global__ void qproj_kernel(const float* __restrict__ query,
                             const float* __restrict__ Wq) {
    __shared__ float qs[Q_];
    int b = blockIdx.y;
    int h = blockIdx.x * blockDim.x + threadIdx.x;
    for (int i = threadIdx.x; i < Q_; i += blockDim.x) qs[i] = query[(size_t)b * Q_ + i];
    __syncthreads();
    const float4* wrow = (const float4*)(Wq + (size_t)h * Q_);
    const float4* q4 = (const float4*)qs;
    float acc = 0.f;
    #pragma unroll 4
    for (int q = 0; q < Q_ / 4; q++) {
        float4 w = wrow[q];
        float4 x = q4[q];
        acc = fmaf(w.x, x.x, acc);
        acc = fmaf(w.y, x.y, acc);
        acc = fmaf(w.z, x.z, acc);
        acc = fmaf(w.w, x.w, acc);
    }
    g_qp[(size_t)b * H_ + h] = acc;
}

// ---------------- 3. energy via mma.sync + ldmatrix + cp.async pipeline ----------------
__device__ __forceinline__ void load_b_async(uint32_t sb, int stage, int h0,
                                             int k0, int tid) {
    #pragma unroll
    for (int i = 0; i < 2; i++) {
        int fi = i * 512 + tid;
        int r = fi >> 2;
        int c = fi & 3;
        size_t gsrc = (size_t)(h0 + r) * K_ + k0 + c * 8;
        uint32_t doff = (uint32_t)(r * B_STR + c * 8) * 2;
        CP_ASYNC16(sb + oB + stage * 20480 + doff, g_WkHi + gsrc);
        CP_ASYNC16(sb + oB + 40960 + stage * 20480 + doff, g_WkLo + gsrc);
    }
}

__device__ __forceinline__ void load_a_regs(const float* __restrict__ keysb,
                                            int s0, int k0, int tid,
                                            float4& f0, float4& f1) {
    int fi0 = tid;
    int fi1 = 512 + tid;
    f0 = *(const float4*)(keysb + (size_t)(s0 + (fi0 >> 3)) * K_ + k0 + (fi0 & 7) * 4);
    f1 = *(const float4*)(keysb + (size_t)(s0 + (fi1 >> 3)) * K_ + k0 + (fi1 & 7) * 4);
}

__device__ __forceinline__ void store_a_split(char* sm, int stage, int tid,
                                              const float4& f, int which) {
    int fi = which * 512 + tid;
    int row = fi >> 3;
    int c4 = fi & 7;
    __nv_bfloat162 h01, h23, l01, l23;
    h01.x = __float2bfloat16(f.x); h01.y = __float2bfloat16(f.y);
    h23.x = __float2bfloat16(f.z); h23.y = __float2bfloat16(f.w);
    l01.x = __float2bfloat16(f.x - __bfloat162float(h01.x));
    l01.y = __float2bfloat16(f.y - __bfloat162float(h01.y));
    l23.x = __float2bfloat16(f.z - __bfloat162float(h23.x));
    l23.y = __float2bfloat16(f.w - __bfloat162float(h23.y));
    int off = (row * A_STR + c4 * 4) * 2;
    *(uint2*)(sm + oA + stage * 10240 + off) = make_uint2(*(uint32_t*)&h01, *(uint32_t*)&h23);
    *(uint2*)(sm + oALO + stage * 10240 + off) = make_uint2(*(uint32_t*)&l01, *(uint32_t*)&l23);
}

__global__ __launch_bounds__(512, 1)
void energy_mma_kernel(const float* __restrict__ keys, const float* __restrict__ v) {
    extern __shared__ char sm[];
    const uint32_t sb = smem_u32(sm);
    float* vs = (float*)(sm + oVS);
    float* qs = (float*)(sm + oQS);
    float* ep = (float*)(sm + oEP);

    const int tid = threadIdx.x;
    const int wid = tid >> 5;
    const int lane = tid & 31;
    const int b = blockIdx.z;
    const int s0 = blockIdx.x * BM;
    const int h0 = blockIdx.y * BN;
    const float* keysb = keys + (size_t)b * S_ * K_;

    if (tid < 256) {
        vs[tid] = v[h0 + tid];
        qs[tid] = g_qp[(size_t)b * H_ + h0 + tid];
    }

    const int wm = wid & 3, wn = wid >> 2;
    const int mbase = wm * 32, nbase = wn * 64;
    const int gid = lane >> 2, qid = lane & 3;

    // ldmatrix per-thread base byte offsets
    const uint32_t aRow = (uint32_t)((mbase + (lane & 15)) * A_STR + (lane >> 4) * 8) * 2;
    const int mB = lane >> 3;
    const uint32_t bRow = (uint32_t)((nbase + (mB >> 1) * 8 + (lane & 7)) * B_STR
                                     + (mB & 1) * 8) * 2;

    float acc[2][8][4];
    #pragma unroll
    for (int mf = 0; mf < 2; mf++)
        #pragma unroll
        for (int nf = 0; nf < 8; nf++)
            #pragma unroll
            for (int r = 0; r < 4; r++) acc[mf][nf][r] = 0.f;

    // prologue: chunk 0
    load_b_async(sb, 0, h0, 0, tid);
    CP_COMMIT();
    float4 fa0, fa1;
    load_a_regs(keysb, s0, 0, tid, fa0, fa1);
    store_a_split(sm, 0, tid, fa0, 0);
    store_a_split(sm, 0, tid, fa1, 1);
    CP_WAIT0();
    __syncthreads();

    for (int kt = 0; kt < NCHUNK; kt++) {
        const int s = kt & 1;
        const bool more = (kt + 1) < NCHUNK;
        if (more) {
            load_b_async(sb, s ^ 1, h0, (kt + 1) * BK, tid);
            CP_COMMIT();
            load_a_regs(keysb, s0, (kt + 1) * BK, tid, fa0, fa1);
        }
        // ---- compute on stage s ----
        const uint32_t aHiBase = sb + oA + s * 10240 + aRow;
        const uint32_t aLoBase = sb + oALO + s * 10240 + aRow;
        const uint32_t bHiBase = sb + oB + s * 20480 + bRow;
        const uint32_t bLoBase = sb + oB + 40960 + s * 20480 + bRow;
        #pragma unroll
        for (int ks = 0; ks < 2; ks++) {
            uint32_t aH[2][4], aL[2][4];
            #pragma unroll
            for (int mf = 0; mf < 2; mf++) {
                ldsm_x4(aH[mf], aHiBase + mf * (16 * A_STR * 2) + ks * 32);
                ldsm_x4(aL[mf], aLoBase + mf * (16 * A_STR * 2) + ks * 32);
            }
            #pragma unroll
            for (int nf2 = 0; nf2 < 4; nf2++) {
                uint32_t bH[4], bL[4];
                ldsm_x4(bH, bHiBase + nf2 * (16 * B_STR * 2) + ks * 32);
                ldsm_x4(bL, bLoBase + nf2 * (16 * B_STR * 2) + ks * 32);
                #pragma unroll
                for (int half = 0; half < 2; half++) {
                    const int nf = nf2 * 2 + half;
                    #pragma unroll
                    for (int mf = 0; mf < 2; mf++) {
                        mma_bf16(acc[mf][nf], aH[mf], bH[half * 2], bH[half * 2 + 1]);
                        mma_bf16(acc[mf][nf], aH[mf], bL[half * 2], bL[half * 2 + 1]);
                        mma_bf16(acc[mf][nf], aL[mf], bH[half * 2], bH[half * 2 + 1]);
                    }
                }
            }
        }
        if (more) {
            store_a_split(sm, s ^ 1, tid, fa0, 0);
            store_a_split(sm, s ^ 1, tid, fa1, 1);
            CP_WAIT0();
        }
        __syncthreads();
    }

    // ---- fused epilogue: e[s] = sum_h v[h] * tanh(qp[h] + D[s,h]) ----
    float epr[2][2] = {{0.f, 0.f}, {0.f, 0.f}};
    #pragma unroll
    for (int mf = 0; mf < 2; mf++) {
        #pragma unroll
        for (int nf = 0; nf < 8; nf++) {
            int hh = nbase + nf * 8 + 2 * qid;
            float v0 = vs[hh], v1 = vs[hh + 1];
            float q0 = qs[hh], q1 = qs[hh + 1];
            epr[mf][0] = fmaf(v0, tanhf(q0 + acc[mf][nf][0]), epr[mf][0]);
            epr[mf][0] = fmaf(v1, tanhf(q1 + acc[mf][nf][1]), epr[mf][0]);
            epr[mf][1] = fmaf(v0, tanhf(q0 + acc[mf][nf][2]), epr[mf][1]);
            epr[mf][1] = fmaf(v1, tanhf(q1 + acc[mf][nf][3]), epr[mf][1]);
        }
    }
    #pragma unroll
    for (int mf = 0; mf < 2; mf++) {
        #pragma unroll
        for (int sbr = 0; sbr < 2; sbr++) {
            float val = epr[mf][sbr];
            val += __shfl_xor_sync(0xFFFFFFFFu, val, 1);
            val += __shfl_xor_sync(0xFFFFFFFFu, val, 2);
            if (qid == 0)
                ep[(mbase + mf * 16 + gid + sbr * 8) * 4 + wn] = val;
        }
    }
    __syncthreads();
    if (tid < BM) {
        float s = ep[tid * 4] + ep[tid * 4 + 1] + ep[tid * 4 + 2] + ep[tid * 4 + 3];
        g_epart[((size_t)b * HT + blockIdx.y) * S_ + s0 + tid] = s;
    }
}

// ---------------- 4. masked softmax over S ----------------
__global__ void softmax_kernel(const void* __restrict__ mask,
                               float* __restrict__ out_attn) {
    __shared__ float es[S_];
    __shared__ float warpred[8];
    __shared__ float s_max, s_sum;
    const int b = blockIdx.x, tid = threadIdx.x;
    const int isbyte = g_mask_flag;
    const unsigned char* mb = (const unsigned char*)mask + (size_t)b * S_;
    const int* mi = (const int*)mask + (size_t)b * S_;

    float lmax = -INFINITY;
    for (int s = tid; s < S_; s += blockDim.x) {
        float e = 0.f;
        #pragma unroll
        for (int t = 0; t < HT; t++) e += g_epart[((size_t)b * HT + t) * S_ + s];
        bool pad = isbyte ? (mb[s] != 0) : (mi[s] != 0);
        if (pad) e = -INFINITY;
        es[s] = e;
        lmax = fmaxf(lmax, e);
    }
    lmax = warpMax(lmax);
    if ((tid & 31) == 0) warpred[tid >> 5] = lmax;
    __syncthreads();
    if (tid == 0) {
        float m = warpred[0];
        for (int i = 1; i < 8; i++) m = fmaxf(m, warpred[i]);
        s_max = m;
    }
    __syncthreads();
    const float m = s_max;
    float lsum = 0.f;
    for (int s = tid; s < S_; s += blockDim.x) {
        float e = es[s];
        float p = (e > -INFINITY) ? expf(e - m) : 0.f;
        es[s] = p;
        lsum += p;
    }
    lsum = warpSum(lsum);
    if ((tid & 31) == 0) warpred[tid >> 5] = lsum;
    __syncthreads();
    if (tid == 0) {
        float t = 0.f;
        for (int i = 0; i < 8; i++) t += warpred[i];
        s_sum = t;
    }
    __syncthreads();
    const float inv = (s_sum > 0.f) ? 1.f / s_sum : 0.f;
    for (int s = tid; s < S_; s += blockDim.x)
        out_attn[(size_t)b * S_ + s] = es[s] * inv;
}

// ---------------- 5. context[b,k] = sum_s attn[b,s] * keys[b,s,k] ----------------
__global__ void context_kernel(const float* __restrict__ keys,
                               const float* __restrict__ attn,
                               float* __restrict__ out_ctx) {
    __shared__ float a_s[S_];
    const int b = blockIdx.y;
    const int k = blockIdx.x * blockDim.x + threadIdx.x;
    for (int s = threadIdx.x; s < S_; s += blockDim.x)
        a_s[s] = attn[(size_t)b * S_ + s];
    __syncthreads();
    const float* kb = keys + (size_t)b * S_ * K_ + k;
    float acc = 0.f;
    #pragma unroll 8
    for (int s = 0; s < S_; s++) acc = fmaf(a_s[s], kb[(size_t)s * K_], acc);
    out_ctx[(size_t)b * K_ + k] = acc;
}

// ---------------- launcher ----------------
extern "C" void kernel_launch(void* const* d_in, const int* in_sizes, int n_in,
                              void* d_out, int out_size) {
    const float* query = (const float*)d_in[0];  // [B,Q]
    const float* keys  = (const float*)d_in[1];  // [B,S,K]
    const void*  mask  = d_in[2];                // [B,S]
    const float* Wq    = (const float*)d_in[3];  // [H,Q]
    const float* Wk    = (const float*)d_in[4];  // [H,K]
    const float* v     = (const float*)d_in[5];  // [1,H]

    float* out      = (float*)d_out;
    float* out_ctx  = out;              // [B,K]
    float* out_attn = out + B_ * K_;    // [B,S]

    cudaFuncSetAttribute(energy_mma_kernel,
                         cudaFuncAttributeMaxDynamicSharedMemorySize, SMEM_E);

    probe_mask_kernel<<<1, 1024>>>((const unsigned char*)mask);
    wk_split_kernel<<<(H_ * K_) / 256, 256>>>(Wk);
    qproj_kernel<<<dim3(H_ / 256, B_), 256>>>(query, Wq);
    energy_mma_kernel<<<dim3(S_ / BM, H_ / BN, B_), 512, SMEM_E>>>(keys, v);
    softmax_kernel<<<B_, 256>>>(mask, out_attn);
    context_kernel<<<dim3(K_ / 256, B_), 256>>>(keys, out_attn, out_ctx);
}

// round 6
// speedup vs baseline: 2.7900x; 1.0591x over previous
#include <cuda_runtime.h>
#include <cuda_bf16.h>
#include <math.h>
#include <stdint.h>

// Problem constants
#define B_ 64
#define S_ 2048
#define H_ 1024
#define K_ 1024
#define Q_ 1024
#define HT 8          // number of 128-wide h tiles (H_/128)

// GEMM tile config (mma.sync m16n8k16 bf16, double-buffered, 2 CTA/SM)
#define BM 128
#define BN 128
#define BK 32
#define A_STR 40      // padded smem row stride (bf16) -> conflict-free
#define B_STR 40
#define NCHUNK (K_ / BK)

// smem byte offsets (dynamic)
// A: hi[s] @ s*10240, lo[s] @ 20480 + s*10240           (0 .. 40960)
// B: hi[s] @ 40960 + s*10240, lo[s] @ 61440 + s*10240   (40960 .. 81920)
#define oA    0
#define oALO  20480
#define oBHI  40960
#define oBLO  61440
#define oVS   81920
#define oQS   82432
#define oEP   82944
#define SMEM_E 84992

// ---------------- device scratch ----------------
__device__ float g_qp[B_ * H_];
__device__ __nv_bfloat16 g_WkHi[H_ * K_];
__device__ __nv_bfloat16 g_WkLo[H_ * K_];
__device__ float g_epart[B_ * HT * S_];
__device__ int   g_mask_flag;

// ---------------- PTX helpers ----------------
__device__ __forceinline__ uint32_t smem_u32(const void* p) {
    uint32_t a;
    asm("{ .reg .u64 t; cvta.to.shared.u64 t, %1; cvt.u32.u64 %0, t; }" : "=r"(a) : "l"(p));
    return a;
}
__device__ __forceinline__ void mma_bf16(float* c, const uint32_t* a,
                                         uint32_t b0, uint32_t b1) {
    asm volatile(
        "mma.sync.aligned.m16n8k16.row.col.f32.bf16.bf16.f32 "
        "{%0,%1,%2,%3}, {%4,%5,%6,%7}, {%8,%9}, {%0,%1,%2,%3};"
        : "+f"(c[0]), "+f"(c[1]), "+f"(c[2]), "+f"(c[3])
        : "r"(a[0]), "r"(a[1]), "r"(a[2]), "r"(a[3]), "r"(b0), "r"(b1));
}
__device__ __forceinline__ void ldsm_x4(uint32_t* r, uint32_t addr) {
    asm volatile("ldmatrix.sync.aligned.m8n8.x4.shared.b16 {%0,%1,%2,%3}, [%4];"
                 : "=r"(r[0]), "=r"(r[1]), "=r"(r[2]), "=r"(r[3]) : "r"(addr));
}
#define CP_ASYNC16(dst, src) \
    asm volatile("cp.async.cg.shared.global [%0], [%1], 16;" :: "r"(dst), "l"(src))
#define CP_COMMIT() asm volatile("cp.async.commit_group;" ::: "memory")
#define CP_WAIT0()  asm volatile("cp.async.wait_group 0;" ::: "memory")

__device__ __forceinline__ float warpMax(float v) {
    #pragma unroll
    for (int o = 16; o; o >>= 1) v = fmaxf(v, __shfl_xor_sync(0xFFFFFFFFu, v, o));
    return v;
}
__device__ __forceinline__ float warpSum(float v) {
    #pragma unroll
    for (int o = 16; o; o >>= 1) v += __shfl_xor_sync(0xFFFFFFFFu, v, o);
    return v;
}

// ---------------- 0. mask dtype probe ----------------
__global__ void probe_mask_kernel(const unsigned char* __restrict__ mask_bytes) {
    __shared__ int red[32];
    int tid = threadIdx.x;
    int cnt = 0;
    for (int i = tid; i < B_ * S_; i += blockDim.x)
        cnt += (mask_bytes[i] != 0);
    #pragma unroll
    for (int o = 16; o; o >>= 1) cnt += __shfl_xor_sync(0xFFFFFFFFu, cnt, o);
    if ((tid & 31) == 0) red[tid >> 5] = cnt;
    __syncthreads();
    if (tid == 0) {
        int total = 0;
        for (int i = 0; i < (int)(blockDim.x >> 5); i++) total += red[i];
        g_mask_flag = (total * 10 > 3 * (B_ * S_)) ? 1 : 0;
    }
}

// ---------------- 1. split Wk into bf16 hi/lo ----------------
__global__ void wk_split_kernel(const float* __restrict__ Wk) {
    int i = blockIdx.x * blockDim.x + threadIdx.x;
    float w = Wk[i];
    __nv_bfloat16 hi = __float2bfloat16(w);
    __nv_bfloat16 lo = __float2bfloat16(w - __bfloat162float(hi));
    g_WkHi[i] = hi;
    g_WkLo[i] = lo;
}

// ---------------- 2. qp[b,h] = sum_q query[b,q] * Wq[h,q] ----------------
__global__ void qproj_kernel(const float* __restrict__ query,
                             const float* __restrict__ Wq) {
    __shared__ float qs[Q_];
    int b = blockIdx.y;
    int h = blockIdx.x * blockDim.x + threadIdx.x;
    for (int i = threadIdx.x; i < Q_; i += blockDim.x) qs[i] = query[(size_t)b * Q_ + i];
    __syncthreads();
    const float4* wrow = (const float4*)(Wq + (size_t)h * Q_);
    const float4* q4 = (const float4*)qs;
    float acc = 0.f;
    #pragma unroll 4
    for (int q = 0; q < Q_ / 4; q++) {
        float4 w = wrow[q];
        float4 x = q4[q];
        acc = fmaf(w.x, x.x, acc);
        acc = fmaf(w.y, x.y, acc);
        acc = fmaf(w.z, x.z, acc);
        acc = fmaf(w.w, x.w, acc);
    }
    g_qp[(size_t)b * H_ + h] = acc;
}

// ---------------- 3. energy via mma.sync + ldmatrix + cp.async, 2 CTA/SM ----------------
__device__ __forceinline__ void load_b_async(uint32_t sb, int stage, int h0,
                                             int k0, int tid) {
    #pragma unroll
    for (int i = 0; i < 2; i++) {
        int fi = i * 256 + tid;
        int r = fi >> 2;
        int c = fi & 3;
        size_t gsrc = (size_t)(h0 + r) * K_ + k0 + c * 8;
        uint32_t doff = (uint32_t)(r * B_STR + c * 8) * 2;
        CP_ASYNC16(sb + oBHI + stage * 10240 + doff, g_WkHi + gsrc);
        CP_ASYNC16(sb + oBLO + stage * 10240 + doff, g_WkLo + gsrc);
    }
}

__device__ __forceinline__ void load_a_regs(const float* __restrict__ keysb,
                                            int s0, int k0, int tid, float4* f) {
    #pragma unroll
    for (int j = 0; j < 4; j++) {
        int fi = j * 256 + tid;
        f[j] = *(const float4*)(keysb + (size_t)(s0 + (fi >> 3)) * K_ + k0 + (fi & 7) * 4);
    }
}

__device__ __forceinline__ void store_a_split(char* sm, int stage, int tid,
                                              const float4* f) {
    #pragma unroll
    for (int j = 0; j < 4; j++) {
        int fi = j * 256 + tid;
        int row = fi >> 3;
        int c4 = fi & 7;
        __nv_bfloat162 h01, h23, l01, l23;
        h01.x = __float2bfloat16(f[j].x); h01.y = __float2bfloat16(f[j].y);
        h23.x = __float2bfloat16(f[j].z); h23.y = __float2bfloat16(f[j].w);
        l01.x = __float2bfloat16(f[j].x - __bfloat162float(h01.x));
        l01.y = __float2bfloat16(f[j].y - __bfloat162float(h01.y));
        l23.x = __float2bfloat16(f[j].z - __bfloat162float(h23.x));
        l23.y = __float2bfloat16(f[j].w - __bfloat162float(h23.y));
        int off = (row * A_STR + c4 * 4) * 2;
        *(uint2*)(sm + oA + stage * 10240 + off) =
            make_uint2(*(uint32_t*)&h01, *(uint32_t*)&h23);
        *(uint2*)(sm + oALO + stage * 10240 + off) =
            make_uint2(*(uint32_t*)&l01, *(uint32_t*)&l23);
    }
}

__global__ __launch_bounds__(256, 2)
void energy_mma_kernel(const float* __restrict__ keys, const float* __restrict__ v) {
    extern __shared__ char sm[];
    const uint32_t sb = smem_u32(sm);
    float* vs = (float*)(sm + oVS);
    float* qs = (float*)(sm + oQS);
    float* ep = (float*)(sm + oEP);

    const int tid = threadIdx.x;
    const int wid = tid >> 5;
    const int lane = tid & 31;
    const int b = blockIdx.z;
    const int s0 = blockIdx.x * BM;
    const int h0 = blockIdx.y * BN;
    const float* keysb = keys + (size_t)b * S_ * K_;

    if (tid < 128) {
        vs[tid] = v[h0 + tid];
        qs[tid] = g_qp[(size_t)b * H_ + h0 + tid];
    }

    const int wm = wid & 3, wn = wid >> 2;       // wm 0..3, wn 0..1
    const int mbase = wm * 32, nbase = wn * 64;
    const int gid = lane >> 2, qid = lane & 3;

    // ldmatrix per-thread base byte offsets
    const uint32_t aRow = (uint32_t)((mbase + (lane & 15)) * A_STR + (lane >> 4) * 8) * 2;
    const int mB = lane >> 3;
    const uint32_t bRow = (uint32_t)((nbase + (mB >> 1) * 8 + (lane & 7)) * B_STR
                                     + (mB & 1) * 8) * 2;

    float acc[2][8][4];
    #pragma unroll
    for (int mf = 0; mf < 2; mf++)
        #pragma unroll
        for (int nf = 0; nf < 8; nf++)
            #pragma unroll
            for (int r = 0; r < 4; r++) acc[mf][nf][r] = 0.f;

    // prologue: chunk 0
    load_b_async(sb, 0, h0, 0, tid);
    CP_COMMIT();
    float4 fa[4];
    load_a_regs(keysb, s0, 0, tid, fa);
    store_a_split(sm, 0, tid, fa);
    CP_WAIT0();
    __syncthreads();

    for (int kt = 0; kt < NCHUNK; kt++) {
        const int s = kt & 1;
        const bool more = (kt + 1) < NCHUNK;
        if (more) {
            load_b_async(sb, s ^ 1, h0, (kt + 1) * BK, tid);
            CP_COMMIT();
            load_a_regs(keysb, s0, (kt + 1) * BK, tid, fa);
        }
        // ---- compute on stage s ----
        const uint32_t aHiBase = sb + oA + s * 10240 + aRow;
        const uint32_t aLoBase = sb + oALO + s * 10240 + aRow;
        const uint32_t bHiBase = sb + oBHI + s * 10240 + bRow;
        const uint32_t bLoBase = sb + oBLO + s * 10240 + bRow;
        #pragma unroll
        for (int ks = 0; ks < 2; ks++) {
            uint32_t aH[2][4], aL[2][4];
            #pragma unroll
            for (int mf = 0; mf < 2; mf++) {
                ldsm_x4(aH[mf], aHiBase + mf * (16 * A_STR * 2) + ks * 32);
                ldsm_x4(aL[mf], aLoBase + mf * (16 * A_STR * 2) + ks * 32);
            }
            #pragma unroll
            for (int nf2 = 0; nf2 < 4; nf2++) {
                uint32_t bH[4], bL[4];
                ldsm_x4(bH, bHiBase + nf2 * (16 * B_STR * 2) + ks * 32);
                ldsm_x4(bL, bLoBase + nf2 * (16 * B_STR * 2) + ks * 32);
                #pragma unroll
                for (int half = 0; half < 2; half++) {
                    const int nf = nf2 * 2 + half;
                    #pragma unroll
                    for (int mf = 0; mf < 2; mf++) {
                        mma_bf16(acc[mf][nf], aH[mf], bH[half * 2], bH[half * 2 + 1]);
                        mma_bf16(acc[mf][nf], aH[mf], bL[half * 2], bL[half * 2 + 1]);
                        mma_bf16(acc[mf][nf], aL[mf], bH[half * 2], bH[half * 2 + 1]);
                    }
                }
            }
        }
        if (more) {
            store_a_split(sm, s ^ 1, tid, fa);
            CP_WAIT0();
        }
        __syncthreads();
    }

    // ---- fused epilogue: e[s] = sum_h v[h] * tanh(qp[h] + D[s,h]) ----
    float epr[2][2] = {{0.f, 0.f}, {0.f, 0.f}};
    #pragma unroll
    for (int mf = 0; mf < 2; mf++) {
        #pragma unroll
        for (int nf = 0; nf < 8; nf++) {
            int hh = nbase + nf * 8 + 2 * qid;
            float v0 = vs[hh], v1 = vs[hh + 1];
            float q0 = qs[hh], q1 = qs[hh + 1];
            epr[mf][0] = fmaf(v0, tanhf(q0 + acc[mf][nf][0]), epr[mf][0]);
            epr[mf][0] = fmaf(v1, tanhf(q1 + acc[mf][nf][1]), epr[mf][0]);
            epr[mf][1] = fmaf(v0, tanhf(q0 + acc[mf][nf][2]), epr[mf][1]);
            epr[mf][1] = fmaf(v1, tanhf(q1 + acc[mf][nf][3]), epr[mf][1]);
        }
    }
    #pragma unroll
    for (int mf = 0; mf < 2; mf++) {
        #pragma unroll
        for (int sbr = 0; sbr < 2; sbr++) {
            float val = epr[mf][sbr];
            val += __shfl_xor_sync(0xFFFFFFFFu, val, 1);
            val += __shfl_xor_sync(0xFFFFFFFFu, val, 2);
            if (qid == 0)
                ep[(mbase + mf * 16 + gid + sbr * 8) * 2 + wn] = val;
        }
    }
    __syncthreads();
    if (tid < BM) {
        float s = ep[tid * 2] + ep[tid * 2 + 1];
        g_epart[((size_t)b * HT + blockIdx.y) * S_ + s0 + tid] = s;
    }
}

// ---------------- 4. masked softmax over S ----------------
__global__ void softmax_kernel(const void* __restrict__ mask,
                               float* __restrict__ out_attn) {
    __shared__ float es[S_];
    __shared__ float warpred[8];
    __shared__ float s_max, s_sum;
    const int b = blockIdx.x, tid = threadIdx.x;
    const int isbyte = g_mask_flag;
    const unsigned char* mb = (const unsigned char*)mask + (size_t)b * S_;
    const int* mi = (const int*)mask + (size_t)b * S_;

    float lmax = -INFINITY;
    for (int s = tid; s < S_; s += blockDim.x) {
        float e = 0.f;
        #pragma unroll
        for (int t = 0; t < HT; t++) e += g_epart[((size_t)b * HT + t) * S_ + s];
        bool pad = isbyte ? (mb[s] != 0) : (mi[s] != 0);
        if (pad) e = -INFINITY;
        es[s] = e;
        lmax = fmaxf(lmax, e);
    }
    lmax = warpMax(lmax);
    if ((tid & 31) == 0) warpred[tid >> 5] = lmax;
    __syncthreads();
    if (tid == 0) {
        float m = warpred[0];
        for (int i = 1; i < 8; i++) m = fmaxf(m, warpred[i]);
        s_max = m;
    }
    __syncthreads();
    const float m = s_max;
    float lsum = 0.f;
    for (int s = tid; s < S_; s += blockDim.x) {
        float e = es[s];
        float p = (e > -INFINITY) ? expf(e - m) : 0.f;
        es[s] = p;
        lsum += p;
    }
    lsum = warpSum(lsum);
    if ((tid & 31) == 0) warpred[tid >> 5] = lsum;
    __syncthreads();
    if (tid == 0) {
        float t = 0.f;
        for (int i = 0; i < 8; i++) t += warpred[i];
        s_sum = t;
    }
    __syncthreads();
    const float inv = (s_sum > 0.f) ? 1.f / s_sum : 0.f;
    for (int s = tid; s < S_; s += blockDim.x)
        out_attn[(size_t)b * S_ + s] = es[s] * inv;
}

// ---------------- 5. context[b,k] = sum_s attn[b,s] * keys[b,s,k] ----------------
__global__ void context_kernel(const float* __restrict__ keys,
                               const float* __restrict__ attn,
                               float* __restrict__ out_ctx) {
    __shared__ float a_s[S_];
    const int b = blockIdx.y;
    const int k = blockIdx.x * blockDim.x + threadIdx.x;
    for (int s = threadIdx.x; s < S_; s += blockDim.x)
        a_s[s] = attn[(size_t)b * S_ + s];
    __syncthreads();
    const float* kb = keys + (size_t)b * S_ * K_ + k;
    float acc = 0.f;
    #pragma unroll 8
    for (int s = 0; s < S_; s++) acc = fmaf(a_s[s], kb[(size_t)s * K_], acc);
    out_ctx[(size_t)b * K_ + k] = acc;
}

// ---------------- launcher ----------------
extern "C" void kernel_launch(void* const* d_in, const int* in_sizes, int n_in,
                              void* d_out, int out_size) {
    const float* query = (const float*)d_in[0];  // [B,Q]
    const float* keys  = (const float*)d_in[1];  // [B,S,K]
    const void*  mask  = d_in[2];                // [B,S]
    const float* Wq    = (const float*)d_in[3];  // [H,Q]
    const float* Wk    = (const float*)d_in[4];  // [H,K]
    const float* v     = (const float*)d_in[5];  // [1,H]

    float* out      = (float*)d_out;
    float* out_ctx  = out;              // [B,K]
    float* out_attn = out + B_ * K_;    // [B,S]

    cudaFuncSetAttribute(energy_mma_kernel,
                         cudaFuncAttributeMaxDynamicSharedMemorySize, SMEM_E);

    probe_mask_kernel<<<1, 1024>>>((const unsigned char*)mask);
    wk_split_kernel<<<(H_ * K_) / 256, 256>>>(Wk);
    qproj_kernel<<<dim3(H_ / 256, B_), 256>>>(query, Wq);
    energy_mma_kernel<<<dim3(S_ / BM, H_ / BN, B_), 256, SMEM_E>>>(keys, v);
    softmax_kernel<<<B_, 256>>>(mask, out_attn);
    context_kernel<<<dim3(K_ / 256, B_), 256>>>(keys, out_attn, out_ctx);
}